// round 1
// baseline (speedup 1.0000x reference)
#include <cuda_runtime.h>
#include <math.h>

// Problem dims (fixed by the reference)
constexpr int BB = 2;
constexpr int NN = 2048;
constexpr int CC = 1024;
constexpr int HH = 8;
constexpr int DH = 128;
constexpr int MALL = BB * NN; // 4096

// Scratch (device globals: allocation-free per harness rules)
__device__ float g_q[(size_t)MALL * CC];
__device__ float g_k[(size_t)MALL * CC];
__device__ float g_v[(size_t)MALL * CC];
__device__ float g_att[(size_t)MALL * CC];

// ---------------------------------------------------------------------------
// GEMM: C[M,1024] = A[M,1024] @ B[1024,1024] + bias   (M = 4096)
// 128x128x16 tiles, 256 threads, 8x8 microtile with strided column halves.
// ---------------------------------------------------------------------------
__global__ __launch_bounds__(256) void sgemm_bias_kernel(
    const float* __restrict__ A, const float* __restrict__ B,
    const float* __restrict__ bias, float* __restrict__ C) {
  constexpr int K = 1024, N = 1024;
  __shared__ float As[16][132];
  __shared__ float Bs[16][132];

  const int tid = threadIdx.x;
  const int bx = blockIdx.x;   // N tile (0..7)
  const int by = blockIdx.y;   // M tile (0..31)
  const int ty = tid >> 4;     // 0..15
  const int tx = tid & 15;     // 0..15

  const float* Ab = A + (size_t)by * 128 * K;
  const float* Bb = B + (size_t)bx * 128;

  const int ar = tid >> 2;            // 0..63
  const int ac = (tid & 3) << 2;      // 0,4,8,12
  const int br = tid >> 5;            // 0..7
  const int bc = (tid & 31) << 2;     // 0..124

  float acc[8][8];
#pragma unroll
  for (int i = 0; i < 8; i++)
#pragma unroll
    for (int j = 0; j < 8; j++) acc[i][j] = 0.f;

  for (int k0 = 0; k0 < K; k0 += 16) {
    float4 a0 = *(const float4*)(Ab + (size_t)ar * K + k0 + ac);
    float4 a1 = *(const float4*)(Ab + (size_t)(ar + 64) * K + k0 + ac);
    float4 b0 = *(const float4*)(Bb + (size_t)(k0 + br) * N + bc);
    float4 b1 = *(const float4*)(Bb + (size_t)(k0 + br + 8) * N + bc);

    As[ac + 0][ar] = a0.x; As[ac + 1][ar] = a0.y;
    As[ac + 2][ar] = a0.z; As[ac + 3][ar] = a0.w;
    As[ac + 0][ar + 64] = a1.x; As[ac + 1][ar + 64] = a1.y;
    As[ac + 2][ar + 64] = a1.z; As[ac + 3][ar + 64] = a1.w;
    *(float4*)&Bs[br][bc] = b0;
    *(float4*)&Bs[br + 8][bc] = b1;
    __syncthreads();

#pragma unroll
    for (int kk = 0; kk < 16; kk++) {
      float4 A0 = *(const float4*)&As[kk][ty * 4];
      float4 A1 = *(const float4*)&As[kk][64 + ty * 4];
      float4 B0 = *(const float4*)&Bs[kk][tx * 4];
      float4 B1 = *(const float4*)&Bs[kk][64 + tx * 4];
      float ra[8] = {A0.x, A0.y, A0.z, A0.w, A1.x, A1.y, A1.z, A1.w};
      float rb[8] = {B0.x, B0.y, B0.z, B0.w, B1.x, B1.y, B1.z, B1.w};
#pragma unroll
      for (int i = 0; i < 8; i++)
#pragma unroll
        for (int j = 0; j < 8; j++) acc[i][j] += ra[i] * rb[j];
    }
    __syncthreads();
  }

#pragma unroll
  for (int i = 0; i < 8; i++) {
    int m = by * 128 + ((i < 4) ? (ty * 4 + i) : (64 + ty * 4 + i - 4));
#pragma unroll
    for (int jh = 0; jh < 2; jh++) {
      int n = bx * 128 + jh * 64 + tx * 4;
      float4 o;
      o.x = acc[i][jh * 4 + 0] + bias[n + 0];
      o.y = acc[i][jh * 4 + 1] + bias[n + 1];
      o.z = acc[i][jh * 4 + 2] + bias[n + 2];
      o.w = acc[i][jh * 4 + 3] + bias[n + 3];
      *(float4*)(C + (size_t)m * N + n) = o;
    }
  }
}

// ---------------------------------------------------------------------------
// Flash-style attention, fp32. Br=128 query rows per CTA, Bc=64 key chunk.
// Layouts in dynamic smem (floats):
//   sQ[128][132], sK[64][132], sV[64][132], sS[128][65], sM[128], sL[128], sA[128]
// ---------------------------------------------------------------------------
constexpr int ATT_BR = 128;
constexpr int ATT_BC = 64;
constexpr int SQ_STR = 132;
constexpr int SS_STR = 65;
constexpr int OFF_Q = 0;                         // 128*132 = 16896
constexpr int OFF_K = OFF_Q + 128 * SQ_STR;      // +8448
constexpr int OFF_V = OFF_K + 64 * SQ_STR;       // +8448
constexpr int OFF_S = OFF_V + 64 * SQ_STR;       // +128*65 = 8320
constexpr int OFF_M = OFF_S + 128 * SS_STR;
constexpr int OFF_L = OFF_M + 128;
constexpr int OFF_A = OFF_L + 128;
constexpr int ATT_SMEM_FLOATS = OFF_A + 128;     // 42496
constexpr int ATT_SMEM_BYTES = ATT_SMEM_FLOATS * 4;  // 169984

__global__ __launch_bounds__(256) void attn_kernel(
    const float* __restrict__ Q, const float* __restrict__ K,
    const float* __restrict__ V, float* __restrict__ O) {
  extern __shared__ float sm[];
  const int tid = threadIdx.x;
  const int bh = blockIdx.y;
  const int b = bh >> 3;
  const int h = bh & 7;
  const int n0 = blockIdx.x * ATT_BR;

  const float* Qb = Q + (size_t)b * NN * CC + (size_t)h * DH;
  const float* Kb = K + (size_t)b * NN * CC + (size_t)h * DH;
  const float* Vb = V + (size_t)b * NN * CC + (size_t)h * DH;
  const float scale = 0.08838834764831845f;  // 1/sqrt(128)

  // Load scaled Q tile (128 x 128) -> sQ
#pragma unroll
  for (int i = 0; i < 16; i++) {
    int l = tid + 256 * i;
    int r = l >> 5;
    int d4 = (l & 31) << 2;
    float4 q = *(const float4*)(Qb + (size_t)(n0 + r) * CC + d4);
    q.x *= scale; q.y *= scale; q.z *= scale; q.w *= scale;
    *(float4*)&sm[OFF_Q + r * SQ_STR + d4] = q;
  }
  if (tid < 128) {
    sm[OFF_M + tid] = -INFINITY;
    sm[OFF_L + tid] = 0.f;
  }

  float acc[8][8];
#pragma unroll
  for (int i = 0; i < 8; i++)
#pragma unroll
    for (int j = 0; j < 8; j++) acc[i][j] = 0.f;

  const int rq = tid & 15;   // PV: rows rq + 16*i
  const int dq = tid >> 4;   // PV: cols 4*dq and 64+4*dq
  const int rg = tid & 31;   // S: rows rg + 32*i
  const int cg = tid >> 5;   // S: cols 4*cg+jj and 32+4*cg+jj (warp-uniform -> broadcast K reads)
  __syncthreads();

  for (int j0 = 0; j0 < NN; j0 += ATT_BC) {
    // Load K, V chunks (64 x 128 each)
#pragma unroll
    for (int i = 0; i < 8; i++) {
      int l = tid + 256 * i;
      int r = l >> 5;
      int d4 = (l & 31) << 2;
      *(float4*)&sm[OFF_K + r * SQ_STR + d4] =
          *(const float4*)(Kb + (size_t)(j0 + r) * CC + d4);
      *(float4*)&sm[OFF_V + r * SQ_STR + d4] =
          *(const float4*)(Vb + (size_t)(j0 + r) * CC + d4);
    }
    __syncthreads();

    // ---- S = Qs @ K^T  (per thread: 4 rows x 8 cols) ----
    float sacc[4][8];
#pragma unroll
    for (int i = 0; i < 4; i++)
#pragma unroll
      for (int j = 0; j < 8; j++) sacc[i][j] = 0.f;

#pragma unroll 2
    for (int d4 = 0; d4 < DH; d4 += 4) {
      float4 qv[4];
#pragma unroll
      for (int i = 0; i < 4; i++)
        qv[i] = *(const float4*)&sm[OFF_Q + (rg + 32 * i) * SQ_STR + d4];
      float4 kv[8];
#pragma unroll
      for (int jj = 0; jj < 4; jj++) {
        kv[jj]     = *(const float4*)&sm[OFF_K + (4 * cg + jj) * SQ_STR + d4];
        kv[4 + jj] = *(const float4*)&sm[OFF_K + (32 + 4 * cg + jj) * SQ_STR + d4];
      }
#pragma unroll
      for (int i = 0; i < 4; i++)
#pragma unroll
        for (int j = 0; j < 8; j++) {
          sacc[i][j] += qv[i].x * kv[j].x;
          sacc[i][j] += qv[i].y * kv[j].y;
          sacc[i][j] += qv[i].z * kv[j].z;
          sacc[i][j] += qv[i].w * kv[j].w;
        }
    }
#pragma unroll
    for (int i = 0; i < 4; i++)
#pragma unroll
      for (int j = 0; j < 8; j++) {
        int c = (j < 4) ? (4 * cg + j) : (32 + 4 * cg + j - 4);
        sm[OFF_S + (rg + 32 * i) * SS_STR + c] = sacc[i][j];
      }
    __syncthreads();

    // ---- online softmax (2 threads per row, 32 entries each) ----
    {
      int r = tid >> 1;
      int c0 = (tid & 1) << 5;
      float* row = &sm[OFF_S + r * SS_STR + c0];
      float mx = row[0];
#pragma unroll
      for (int n = 1; n < 32; n++) mx = fmaxf(mx, row[n]);
      mx = fmaxf(mx, __shfl_xor_sync(0xffffffffu, mx, 1));
      float mo = sm[OFF_M + r];
      float mn = fmaxf(mo, mx);
      float al = __expf(mo - mn);
      float s = 0.f;
#pragma unroll
      for (int n = 0; n < 32; n++) {
        float p = __expf(row[n] - mn);
        row[n] = p;
        s += p;
      }
      s += __shfl_xor_sync(0xffffffffu, s, 1);
      if ((tid & 1) == 0) {
        sm[OFF_M + r] = mn;
        sm[OFF_A + r] = al;
        sm[OFF_L + r] = sm[OFF_L + r] * al + s;
      }
    }
    __syncthreads();

    // ---- rescale + PV accumulation (per thread: 8 rows x 8 cols) ----
    {
      float al[8];
#pragma unroll
      for (int i = 0; i < 8; i++) al[i] = sm[OFF_A + rq + 16 * i];
#pragma unroll
      for (int i = 0; i < 8; i++)
#pragma unroll
        for (int u = 0; u < 8; u++) acc[i][u] *= al[i];

#pragma unroll 4
      for (int j = 0; j < ATT_BC; j++) {
        float4 v0 = *(const float4*)&sm[OFF_V + j * SQ_STR + 4 * dq];
        float4 v1 = *(const float4*)&sm[OFF_V + j * SQ_STR + 64 + 4 * dq];
#pragma unroll
        for (int i = 0; i < 8; i++) {
          float p = sm[OFF_S + (rq + 16 * i) * SS_STR + j];
          acc[i][0] += p * v0.x; acc[i][1] += p * v0.y;
          acc[i][2] += p * v0.z; acc[i][3] += p * v0.w;
          acc[i][4] += p * v1.x; acc[i][5] += p * v1.y;
          acc[i][6] += p * v1.z; acc[i][7] += p * v1.w;
        }
      }
    }
    __syncthreads();
  }

  // ---- epilogue: O = acc / l ----
  float* Ob = O + (size_t)b * NN * CC + (size_t)h * DH;
#pragma unroll
  for (int i = 0; i < 8; i++) {
    float inv = 1.0f / sm[OFF_L + rq + 16 * i];
    float4 o0, o1;
    o0.x = acc[i][0] * inv; o0.y = acc[i][1] * inv;
    o0.z = acc[i][2] * inv; o0.w = acc[i][3] * inv;
    o1.x = acc[i][4] * inv; o1.y = acc[i][5] * inv;
    o1.z = acc[i][6] * inv; o1.w = acc[i][7] * inv;
    size_t base = (size_t)(n0 + rq + 16 * i) * CC;
    *(float4*)(Ob + base + 4 * dq) = o0;
    *(float4*)(Ob + base + 64 + 4 * dq) = o1;
  }
}

// ---------------------------------------------------------------------------
// Launch
// ---------------------------------------------------------------------------
extern "C" void kernel_launch(void* const* d_in, const int* in_sizes, int n_in,
                              void* d_out, int out_size) {
  const float* xq = (const float*)d_in[0];
  const float* xkv = (const float*)d_in[1];
  const float* Wq = (const float*)d_in[2];
  const float* bq = (const float*)d_in[3];
  const float* Wk = (const float*)d_in[4];
  const float* bk = (const float*)d_in[5];
  const float* Wv = (const float*)d_in[6];
  const float* bv = (const float*)d_in[7];
  const float* Wo = (const float*)d_in[8];
  const float* bo = (const float*)d_in[9];
  float* out = (float*)d_out;

  float *q, *k, *v, *att;
  cudaGetSymbolAddress((void**)&q, g_q);
  cudaGetSymbolAddress((void**)&k, g_k);
  cudaGetSymbolAddress((void**)&v, g_v);
  cudaGetSymbolAddress((void**)&att, g_att);

  cudaFuncSetAttribute(attn_kernel, cudaFuncAttributeMaxDynamicSharedMemorySize,
                       ATT_SMEM_BYTES);

  dim3 gg(CC / 128, MALL / 128);  // (8, 32)
  sgemm_bias_kernel<<<gg, 256>>>(xq, Wq, bq, q);
  sgemm_bias_kernel<<<gg, 256>>>(xkv, Wk, bk, k);
  sgemm_bias_kernel<<<gg, 256>>>(xkv, Wv, bv, v);
  attn_kernel<<<dim3(NN / ATT_BR, BB * HH), 256, ATT_SMEM_BYTES>>>(q, k, v, att);
  sgemm_bias_kernel<<<gg, 256>>>(att, Wo, bo, out);
}

// round 3
// speedup vs baseline: 2.5847x; 2.5847x over previous
#include <cuda_runtime.h>
#include <math.h>

constexpr int BB = 2;
constexpr int NN = 2048;
constexpr int CC = 1024;
constexpr int HH = 8;
constexpr int DH = 128;
constexpr int MALL = BB * NN;  // 4096

__device__ float g_q[(size_t)MALL * CC];
__device__ float g_k[(size_t)MALL * CC];
__device__ float g_v[(size_t)MALL * CC];
__device__ float g_att[(size_t)MALL * CC];

// ---------------------------------------------------------------------------
// tf32 helpers
// ---------------------------------------------------------------------------
__device__ __forceinline__ float f2tf(float x) {
  unsigned u;
  asm("cvt.rna.tf32.f32 %0, %1;" : "=r"(u) : "f"(x));
  return __uint_as_float(u);
}
__device__ __forceinline__ unsigned fu(float x) { return __float_as_uint(x); }

// D += A(16x8) * B(8x8), tf32, row.col
__device__ __forceinline__ void mma8(float* c, const unsigned* a, unsigned b0,
                                     unsigned b1) {
  asm volatile(
      "mma.sync.aligned.m16n8k8.row.col.f32.tf32.tf32.f32 "
      "{%0,%1,%2,%3}, {%4,%5,%6,%7}, {%8,%9}, {%0,%1,%2,%3};"
      : "+f"(c[0]), "+f"(c[1]), "+f"(c[2]), "+f"(c[3])
      : "r"(a[0]), "r"(a[1]), "r"(a[2]), "r"(a[3]), "r"(b0), "r"(b1));
}

// ---------------------------------------------------------------------------
// GEMM: C[4096,1024] = A @ B + bias, tf32 tensor-core, 128x128x32 tiles.
// 8 warps (4m x 2n), warp tile 32x64, m16n8k8 fragments. Register prefetch.
// FIXED: full-tile loads (4 float4 per thread per tile).
// ---------------------------------------------------------------------------
__global__ __launch_bounds__(256) void sgemm_tf32_kernel(
    const float* __restrict__ A, const float* __restrict__ B,
    const float* __restrict__ bias, float* __restrict__ C) {
  constexpr int K = 1024, N = 1024;
  __shared__ float As[128][36];   // [m][k]
  __shared__ float Bs[32][136];   // [k][n]

  const int tid = threadIdx.x;
  const int warp = tid >> 5, lane = tid & 31;
  const int g = lane >> 2, t = lane & 3;
  const int wm = warp & 3, wn = warp >> 2;
  const int bx = blockIdx.x, by = blockIdx.y;

  const int ar = tid >> 3, ac = (tid & 7) * 4;    // A: 32 rows/pass x 4 passes
  const int bkr = tid >> 5, bc = (tid & 31) * 4;  // B: 8 rows/pass x 4 passes

  float acc[2][8][4];
#pragma unroll
  for (int mt = 0; mt < 2; mt++)
#pragma unroll
    for (int nt = 0; nt < 8; nt++)
#pragma unroll
      for (int i = 0; i < 4; i++) acc[mt][nt][i] = 0.f;

  float4 pa[4], pb[4];
#pragma unroll
  for (int i = 0; i < 4; i++) {
    pa[i] = *(const float4*)(A + (size_t)(by * 128 + ar + 32 * i) * K + ac);
    pb[i] = *(const float4*)(B + (size_t)(bkr + 8 * i) * N + bx * 128 + bc);
  }

  for (int k0 = 0; k0 < K; k0 += 32) {
#pragma unroll
    for (int i = 0; i < 4; i++) {
      As[ar + 32 * i][ac + 0] = f2tf(pa[i].x);
      As[ar + 32 * i][ac + 1] = f2tf(pa[i].y);
      As[ar + 32 * i][ac + 2] = f2tf(pa[i].z);
      As[ar + 32 * i][ac + 3] = f2tf(pa[i].w);
      Bs[bkr + 8 * i][bc + 0] = f2tf(pb[i].x);
      Bs[bkr + 8 * i][bc + 1] = f2tf(pb[i].y);
      Bs[bkr + 8 * i][bc + 2] = f2tf(pb[i].z);
      Bs[bkr + 8 * i][bc + 3] = f2tf(pb[i].w);
    }
    __syncthreads();

    if (k0 + 32 < K) {
#pragma unroll
      for (int i = 0; i < 4; i++) {
        pa[i] = *(const float4*)(A + (size_t)(by * 128 + ar + 32 * i) * K +
                                 k0 + 32 + ac);
        pb[i] = *(const float4*)(B + (size_t)(k0 + 32 + bkr + 8 * i) * N +
                                 bx * 128 + bc);
      }
    }

#pragma unroll
    for (int ks = 0; ks < 4; ks++) {
      const int kk = ks * 8;
      unsigned afr[2][4];
#pragma unroll
      for (int mt = 0; mt < 2; mt++) {
        const int rr = wm * 32 + mt * 16;
        afr[mt][0] = fu(As[rr + g][kk + t]);
        afr[mt][1] = fu(As[rr + g + 8][kk + t]);
        afr[mt][2] = fu(As[rr + g][kk + t + 4]);
        afr[mt][3] = fu(As[rr + g + 8][kk + t + 4]);
      }
#pragma unroll
      for (int nt = 0; nt < 8; nt++) {
        const int cc = wn * 64 + nt * 8 + g;
        unsigned b0 = fu(Bs[kk + t][cc]);
        unsigned b1 = fu(Bs[kk + t + 4][cc]);
        mma8(acc[0][nt], afr[0], b0, b1);
        mma8(acc[1][nt], afr[1], b0, b1);
      }
    }
    __syncthreads();
  }

#pragma unroll
  for (int mt = 0; mt < 2; mt++) {
    const int r0 = by * 128 + wm * 32 + mt * 16 + g;
#pragma unroll
    for (int nt = 0; nt < 8; nt++) {
      const int c = bx * 128 + wn * 64 + nt * 8 + 2 * t;
      const float bx0 = bias[c], bx1 = bias[c + 1];
      float2 o0 = {acc[mt][nt][0] + bx0, acc[mt][nt][1] + bx1};
      float2 o1 = {acc[mt][nt][2] + bx0, acc[mt][nt][3] + bx1};
      *(float2*)(C + (size_t)r0 * N + c) = o0;
      *(float2*)(C + (size_t)(r0 + 8) * N + c) = o1;
    }
  }
}

// ---------------------------------------------------------------------------
// Flash attention, tf32 tensor-core. Br=128, Bc=64.
// smem: sQ[128][136], sK[64][136], sV[64][136], sS[128][68], sM/L/A[128]
// ---------------------------------------------------------------------------
constexpr int SQ_STR = 136;
constexpr int SS_STR = 68;
constexpr int OFF_Q = 0;
constexpr int OFF_K = OFF_Q + 128 * SQ_STR;
constexpr int OFF_V = OFF_K + 64 * SQ_STR;
constexpr int OFF_S = OFF_V + 64 * SQ_STR;
constexpr int OFF_M = OFF_S + 128 * SS_STR;
constexpr int OFF_L = OFF_M + 128;
constexpr int OFF_A = OFF_L + 128;
constexpr int ATT_SMEM_BYTES = (OFF_A + 128) * 4;  // 175,616 B

__global__ __launch_bounds__(256) void attn_tf32_kernel(
    const float* __restrict__ Q, const float* __restrict__ K,
    const float* __restrict__ V, float* __restrict__ O) {
  extern __shared__ float sm[];
  const int tid = threadIdx.x;
  const int warp = tid >> 5, lane = tid & 31;
  const int g = lane >> 2, t = lane & 3;
  const int wm = warp & 3, wn = warp >> 2;
  const int bh = blockIdx.y;
  const int b = bh >> 3, h = bh & 7;
  const int n0 = blockIdx.x * 128;

  const float* Qb = Q + (size_t)b * NN * CC + (size_t)h * DH;
  const float* Kb = K + (size_t)b * NN * CC + (size_t)h * DH;
  const float* Vb = V + (size_t)b * NN * CC + (size_t)h * DH;
  const float scale = 0.08838834764831845f;  // 1/sqrt(128)

  // Q tile (scaled, tf32-rounded)
#pragma unroll
  for (int i = 0; i < 16; i++) {
    int l = tid + 256 * i;
    int r = l >> 5, d4 = (l & 31) << 2;
    float4 q = *(const float4*)(Qb + (size_t)(n0 + r) * CC + d4);
    sm[OFF_Q + r * SQ_STR + d4 + 0] = f2tf(q.x * scale);
    sm[OFF_Q + r * SQ_STR + d4 + 1] = f2tf(q.y * scale);
    sm[OFF_Q + r * SQ_STR + d4 + 2] = f2tf(q.z * scale);
    sm[OFF_Q + r * SQ_STR + d4 + 3] = f2tf(q.w * scale);
  }
  if (tid < 128) {
    sm[OFF_M + tid] = -INFINITY;
    sm[OFF_L + tid] = 0.f;
  }

  float oacc[2][8][4];
#pragma unroll
  for (int mt = 0; mt < 2; mt++)
#pragma unroll
    for (int nt = 0; nt < 8; nt++)
#pragma unroll
      for (int i = 0; i < 4; i++) oacc[mt][nt][i] = 0.f;
  __syncthreads();

  for (int j0 = 0; j0 < NN; j0 += 64) {
    // K/V chunk load (tf32-rounded)
#pragma unroll
    for (int i = 0; i < 8; i++) {
      int l = tid + 256 * i;
      int r = l >> 5, d4 = (l & 31) << 2;
      float4 kv = *(const float4*)(Kb + (size_t)(j0 + r) * CC + d4);
      float4 vv = *(const float4*)(Vb + (size_t)(j0 + r) * CC + d4);
      sm[OFF_K + r * SQ_STR + d4 + 0] = f2tf(kv.x);
      sm[OFF_K + r * SQ_STR + d4 + 1] = f2tf(kv.y);
      sm[OFF_K + r * SQ_STR + d4 + 2] = f2tf(kv.z);
      sm[OFF_K + r * SQ_STR + d4 + 3] = f2tf(kv.w);
      sm[OFF_V + r * SQ_STR + d4 + 0] = f2tf(vv.x);
      sm[OFF_V + r * SQ_STR + d4 + 1] = f2tf(vv.y);
      sm[OFF_V + r * SQ_STR + d4 + 2] = f2tf(vv.z);
      sm[OFF_V + r * SQ_STR + d4 + 3] = f2tf(vv.w);
    }
    __syncthreads();

    // ---- S = Qs @ Ks^T: warp tile 32 rows x 32 cols, 16 k-steps ----
    float sacc[2][4][4];
#pragma unroll
    for (int mt = 0; mt < 2; mt++)
#pragma unroll
      for (int nt = 0; nt < 4; nt++)
#pragma unroll
        for (int i = 0; i < 4; i++) sacc[mt][nt][i] = 0.f;

#pragma unroll
    for (int ks = 0; ks < 16; ks++) {
      const int kk = ks * 8;
      unsigned afr[2][4];
#pragma unroll
      for (int mt = 0; mt < 2; mt++) {
        const int rr = wm * 32 + mt * 16;
        afr[mt][0] = fu(sm[OFF_Q + (rr + g) * SQ_STR + kk + t]);
        afr[mt][1] = fu(sm[OFF_Q + (rr + g + 8) * SQ_STR + kk + t]);
        afr[mt][2] = fu(sm[OFF_Q + (rr + g) * SQ_STR + kk + t + 4]);
        afr[mt][3] = fu(sm[OFF_Q + (rr + g + 8) * SQ_STR + kk + t + 4]);
      }
#pragma unroll
      for (int nt = 0; nt < 4; nt++) {
        const int cc = wn * 32 + nt * 8 + g;
        unsigned b0 = fu(sm[OFF_K + cc * SQ_STR + kk + t]);
        unsigned b1 = fu(sm[OFF_K + cc * SQ_STR + kk + t + 4]);
        mma8(sacc[0][nt], afr[0], b0, b1);
        mma8(sacc[1][nt], afr[1], b0, b1);
      }
    }
#pragma unroll
    for (int mt = 0; mt < 2; mt++) {
      const int r0 = wm * 32 + mt * 16 + g;
#pragma unroll
      for (int nt = 0; nt < 4; nt++) {
        const int c = wn * 32 + nt * 8 + 2 * t;
        *(float2*)&sm[OFF_S + r0 * SS_STR + c] =
            make_float2(sacc[mt][nt][0], sacc[mt][nt][1]);
        *(float2*)&sm[OFF_S + (r0 + 8) * SS_STR + c] =
            make_float2(sacc[mt][nt][2], sacc[mt][nt][3]);
      }
    }
    __syncthreads();

    // ---- online softmax: 2 threads per row, 32 entries each ----
    {
      int r = tid >> 1;
      int c0 = (tid & 1) << 5;
      float* row = &sm[OFF_S + r * SS_STR + c0];
      float mx = row[0];
#pragma unroll
      for (int n = 1; n < 32; n++) mx = fmaxf(mx, row[n]);
      mx = fmaxf(mx, __shfl_xor_sync(0xffffffffu, mx, 1));
      float mo = sm[OFF_M + r];
      float mn = fmaxf(mo, mx);
      float al = __expf(mo - mn);
      float s = 0.f;
#pragma unroll
      for (int n = 0; n < 32; n++) {
        float p = f2tf(__expf(row[n] - mn));  // round so L matches PV inputs
        row[n] = p;
        s += p;
      }
      s += __shfl_xor_sync(0xffffffffu, s, 1);
      if ((tid & 1) == 0) {
        sm[OFF_M + r] = mn;
        sm[OFF_A + r] = al;
        sm[OFF_L + r] = sm[OFF_L + r] * al + s;
      }
    }
    __syncthreads();

    // ---- PV: O += P @ V: warp tile 32 rows x 64 cols, 8 k-steps ----
    {
      float al0[2], al1[2];
#pragma unroll
      for (int mt = 0; mt < 2; mt++) {
        al0[mt] = sm[OFF_A + wm * 32 + mt * 16 + g];
        al1[mt] = sm[OFF_A + wm * 32 + mt * 16 + g + 8];
      }
#pragma unroll
      for (int mt = 0; mt < 2; mt++)
#pragma unroll
        for (int nt = 0; nt < 8; nt++) {
          oacc[mt][nt][0] *= al0[mt];
          oacc[mt][nt][1] *= al0[mt];
          oacc[mt][nt][2] *= al1[mt];
          oacc[mt][nt][3] *= al1[mt];
        }

#pragma unroll
      for (int ks = 0; ks < 8; ks++) {
        const int kk = ks * 8;
        unsigned afr[2][4];
#pragma unroll
        for (int mt = 0; mt < 2; mt++) {
          const int rr = wm * 32 + mt * 16;
          afr[mt][0] = fu(sm[OFF_S + (rr + g) * SS_STR + kk + t]);
          afr[mt][1] = fu(sm[OFF_S + (rr + g + 8) * SS_STR + kk + t]);
          afr[mt][2] = fu(sm[OFF_S + (rr + g) * SS_STR + kk + t + 4]);
          afr[mt][3] = fu(sm[OFF_S + (rr + g + 8) * SS_STR + kk + t + 4]);
        }
#pragma unroll
        for (int nt = 0; nt < 8; nt++) {
          const int cc = wn * 64 + nt * 8 + g;
          unsigned b0 = fu(sm[OFF_V + (kk + t) * SQ_STR + cc]);
          unsigned b1 = fu(sm[OFF_V + (kk + t + 4) * SQ_STR + cc]);
          mma8(oacc[0][nt], afr[0], b0, b1);
          mma8(oacc[1][nt], afr[1], b0, b1);
        }
      }
    }
    __syncthreads();
  }

  // ---- epilogue ----
  float* Ob = O + (size_t)b * NN * CC + (size_t)h * DH;
#pragma unroll
  for (int mt = 0; mt < 2; mt++) {
    const int r0 = wm * 32 + mt * 16 + g;
    const float inv0 = 1.0f / sm[OFF_L + r0];
    const float inv1 = 1.0f / sm[OFF_L + r0 + 8];
#pragma unroll
    for (int nt = 0; nt < 8; nt++) {
      const int c = wn * 64 + nt * 8 + 2 * t;
      *(float2*)(Ob + (size_t)(n0 + r0) * CC + c) =
          make_float2(oacc[mt][nt][0] * inv0, oacc[mt][nt][1] * inv0);
      *(float2*)(Ob + (size_t)(n0 + r0 + 8) * CC + c) =
          make_float2(oacc[mt][nt][2] * inv1, oacc[mt][nt][3] * inv1);
    }
  }
}

// ---------------------------------------------------------------------------
extern "C" void kernel_launch(void* const* d_in, const int* in_sizes, int n_in,
                              void* d_out, int out_size) {
  const float* xq = (const float*)d_in[0];
  const float* xkv = (const float*)d_in[1];
  const float* Wq = (const float*)d_in[2];
  const float* bq = (const float*)d_in[3];
  const float* Wk = (const float*)d_in[4];
  const float* bk = (const float*)d_in[5];
  const float* Wv = (const float*)d_in[6];
  const float* bv = (const float*)d_in[7];
  const float* Wo = (const float*)d_in[8];
  const float* bo = (const float*)d_in[9];
  float* out = (float*)d_out;

  float *q, *k, *v, *att;
  cudaGetSymbolAddress((void**)&q, g_q);
  cudaGetSymbolAddress((void**)&k, g_k);
  cudaGetSymbolAddress((void**)&v, g_v);
  cudaGetSymbolAddress((void**)&att, g_att);

  cudaFuncSetAttribute(attn_tf32_kernel,
                       cudaFuncAttributeMaxDynamicSharedMemorySize,
                       ATT_SMEM_BYTES);

  dim3 gg(CC / 128, MALL / 128);  // (8, 32)
  sgemm_tf32_kernel<<<gg, 256>>>(xq, Wq, bq, q);
  sgemm_tf32_kernel<<<gg, 256>>>(xkv, Wk, bk, k);
  sgemm_tf32_kernel<<<gg, 256>>>(xkv, Wv, bv, v);
  attn_tf32_kernel<<<dim3(NN / 128, BB * HH), 256, ATT_SMEM_BYTES>>>(q, k, v,
                                                                     att);
  sgemm_tf32_kernel<<<gg, 256>>>(att, Wo, bo, out);
}